// round 1
// baseline (speedup 1.0000x reference)
#include <cuda_runtime.h>
#include <cstdint>

#define NB 4096
#define H1 32
#define H2 32
#define DD 32
#define NC 64
#define CTILE 8
#define WARPS_PER_BLOCK 8

__device__ __forceinline__ unsigned long long pack2(float lo, float hi) {
    unsigned long long r;
    asm("mov.b64 %0, {%1, %2};" : "=l"(r) : "f"(lo), "f"(hi));
    return r;
}
__device__ __forceinline__ void unpack2(unsigned long long v, float& lo, float& hi) {
    asm("mov.b64 {%0, %1}, %2;" : "=f"(lo), "=f"(hi) : "l"(v));
}
// Packed dual-fp32 FMA (sm_103a FFMA2). Exact per-lane IEEE fp32, so
// results are bit-identical to scalar fmaf accumulation order used here.
__device__ __forceinline__ unsigned long long fma2(unsigned long long a,
                                                   unsigned long long b,
                                                   unsigned long long c) {
    unsigned long long d;
    asm("fma.rn.f32x2 %0, %1, %2, %3;" : "=l"(d) : "l"(a), "l"(b), "l"(c));
    return d;
}

__global__ __launch_bounds__(WARPS_PER_BLOCK * 32, 2)
void cin_kernel(const float* __restrict__ x,
                const float* __restrict__ y,
                const float* __restrict__ K,
                float* __restrict__ out_mat,
                float* __restrict__ out_fin) {
    // 8 c-channels staged at a time: 8 * 32 * 32 * 4 = 32 KB
    __shared__ float sK[CTILE * H1 * H2];

    const int warp = threadIdx.x >> 5;
    const int lane = threadIdx.x & 31;
    const int b = blockIdx.x * WARPS_PER_BLOCK + warp;   // one warp per batch row

    // Per-lane column d = lane. Load x[b,:,d] and y[b,:,d] (coalesced across lanes).
    const float* xb = x + (size_t)b * H1 * DD;
    const float* yb = y + (size_t)b * H2 * DD;

    float xr[H1];
#pragma unroll
    for (int i = 0; i < H1; i++) xr[i] = xb[i * DD + lane];

    unsigned long long y2[H2 / 2];
#pragma unroll
    for (int j = 0; j < H2 / 2; j++) {
        float a  = yb[(2 * j) * DD + lane];
        float bb = yb[(2 * j + 1) * DD + lane];
        y2[j] = pack2(a, bb);
    }

    float* omb = out_mat + (size_t)b * NC * DD;
    float* ofb = out_fin + (size_t)b * NC;

    for (int ct = 0; ct < NC; ct += CTILE) {
        // Stage K[ct:ct+CTILE] into SMEM (coalesced float4 copy).
        {
            const float4* Kg  = (const float4*)(K + (size_t)ct * H1 * H2);
            float4*       sK4 = (float4*)sK;
            for (int idx = threadIdx.x; idx < CTILE * H1 * H2 / 4;
                 idx += WARPS_PER_BLOCK * 32)
                sK4[idx] = Kg[idx];
        }
        __syncthreads();

#pragma unroll 1
        for (int cc = 0; cc < CTILE; cc++) {
            // K row for channel c: broadcast LDS.128 across the warp (conflict-free).
            const ulonglong2* k4 =
                (const ulonglong2*)(sK + cc * H1 * H2);

            float acc = 0.0f;
#pragma unroll 4
            for (int i = 0; i < H1; i++) {
                unsigned long long t2a = 0ull;  // packed (0.f, 0.f)
                unsigned long long t2b = 0ull;
#pragma unroll
                for (int jj = 0; jj < H2 / 4; jj++) {
                    ulonglong2 kv = k4[i * (H2 / 4) + jj];
                    t2a = fma2(kv.x, y2[2 * jj],     t2a);
                    t2b = fma2(kv.y, y2[2 * jj + 1], t2b);
                }
                float l0, h0, l1, h1;
                unpack2(t2a, l0, h0);
                unpack2(t2b, l1, h1);
                acc = fmaf(xr[i], (l0 + h0) + (l1 + h1), acc);
            }

            // output_mat[b, c, d]
            omb[(ct + cc) * DD + lane] = acc;

            // final_output[b, c] = sum over d (warp reduction over lanes)
            float s = acc;
#pragma unroll
            for (int o = 16; o > 0; o >>= 1)
                s += __shfl_xor_sync(0xffffffffu, s, o);
            if (lane == 0) ofb[ct + cc] = s;
        }
        __syncthreads();
    }
}

extern "C" void kernel_launch(void* const* d_in, const int* in_sizes, int n_in,
                              void* d_out, int out_size) {
    const float* x = (const float*)d_in[0];
    const float* y = (const float*)d_in[1];
    const float* K = (const float*)d_in[2];
    float* out_mat = (float*)d_out;
    float* out_fin = out_mat + (size_t)NB * NC * DD;  // tuple order: (output_mat, final)

    cin_kernel<<<NB / WARPS_PER_BLOCK, WARPS_PER_BLOCK * 32>>>(
        x, y, K, out_mat, out_fin);
}

// round 3
// speedup vs baseline: 3.6741x; 3.6741x over previous
#include <cuda_runtime.h>
#include <cuda_bf16.h>
#include <cstdint>

#define NB 4096
#define NC 64
#define DD 32
#define KK 1024   // H1*H2

// ---------------------------------------------------------------- W fragments
// Pre-split kernel matrix into bf16 hi/lo, laid out per mma.sync A-fragment:
// Wfrag[chunk(64)][mtile(4)][lane(32)][reg(4)] as u32(bf16x2).
// A fragment (m16n8k16 row-major): a0=(r, kc|kc+1) a1=(r+8, ..) a2=(r, kc+8..) a3=(r+8, kc+8..)
// with r = 16*mt + lane/4, kc = 16*chunk + (lane%4)*2.
__device__ __align__(16) uint32_t g_WfragHi[64 * 4 * 32 * 4];
__device__ __align__(16) uint32_t g_WfragLo[64 * 4 * 32 * 4];

__global__ void wfrag_kernel(const float* __restrict__ K) {
    int idx = blockIdx.x * blockDim.x + threadIdx.x;  // 8192
    int lane = idx & 31;
    int mt = (idx >> 5) & 3;
    int ch = idx >> 7;
    int r0 = 16 * mt + (lane >> 2);
    int kc = 16 * ch + (lane & 3) * 2;
    uint32_t hi[4], lo[4];
#pragma unroll
    for (int q = 0; q < 4; q++) {
        int r = r0 + (q & 1) * 8;
        int c = kc + (q >> 1) * 8;
        float w0 = K[r * KK + c], w1 = K[r * KK + c + 1];
        __nv_bfloat16 h0 = __float2bfloat16_rn(w0);
        __nv_bfloat16 h1 = __float2bfloat16_rn(w1);
        __nv_bfloat16 l0 = __float2bfloat16_rn(w0 - __bfloat162float(h0));
        __nv_bfloat16 l1 = __float2bfloat16_rn(w1 - __bfloat162float(h1));
        hi[q] = (uint32_t)__bfloat16_as_ushort(h0) |
                ((uint32_t)__bfloat16_as_ushort(h1) << 16);
        lo[q] = (uint32_t)__bfloat16_as_ushort(l0) |
                ((uint32_t)__bfloat16_as_ushort(l1) << 16);
    }
    *(uint4*)&g_WfragHi[idx * 4] = make_uint4(hi[0], hi[1], hi[2], hi[3]);
    *(uint4*)&g_WfragLo[idx * 4] = make_uint4(lo[0], lo[1], lo[2], lo[3]);
}

// ---------------------------------------------------------------- helpers
__device__ __forceinline__ uint32_t bf16x2_of(float hi, float lo) {
    uint32_t r;
    asm("cvt.rn.bf16x2.f32 %0, %1, %2;" : "=r"(r) : "f"(hi), "f"(lo));
    return r;
}
__device__ __forceinline__ void mma_bf16(float& c0, float& c1, float& c2, float& c3,
                                         uint32_t a0, uint32_t a1, uint32_t a2,
                                         uint32_t a3, uint32_t b0, uint32_t b1) {
    asm volatile(
        "mma.sync.aligned.m16n8k16.row.col.f32.bf16.bf16.f32 "
        "{%0,%1,%2,%3}, {%4,%5,%6,%7}, {%8,%9}, {%0,%1,%2,%3};"
        : "+f"(c0), "+f"(c1), "+f"(c2), "+f"(c3)
        : "r"(a0), "r"(a1), "r"(a2), "r"(a3), "r"(b0), "r"(b1));
}

// ---------------------------------------------------------------- main kernel
// CTA: 256 threads = 8 warps = 2 batches. Warp (w&3) covers d in [8*(w&3), +8).
// Per-batch GEMM: OUT[c(64), d(32)] = W[c, k] * Z[k, d], K=1024, 64 k16-chunks.
__global__ __launch_bounds__(256, 2)
void cin_mma_kernel(const float* __restrict__ X, const float* __restrict__ Y,
                    float* __restrict__ out_mat, float* __restrict__ out_fin) {
    __shared__ float pfin[2][NC];

    const int t = threadIdx.x;
    const int lane = t & 31;
    const int w = t >> 5;
    const int bl = w >> 2;
    const int dbase = (w & 3) * 8;
    const int b = blockIdx.x * 2 + bl;
    const int dB = dbase + (lane >> 2);   // d this thread supplies to B fragments
    const int jm = (lane & 3) * 2;        // j phase for B fragment k-slots

    if (t < 2 * NC) ((float*)pfin)[t] = 0.0f;
    __syncthreads();

    // x[b, :, dB] (all 32 i) and the 8 y values this thread's B slots need:
    // y8[2a+e] = y[b, 8a + jm + e, dB]
    const float* xb = X + (size_t)b * KK + dB;
    const float* yb = Y + (size_t)b * KK + dB;
    float xv[32];
#pragma unroll
    for (int i = 0; i < 32; i++) xv[i] = xb[i * 32];
    float y8[8];
#pragma unroll
    for (int a = 0; a < 4; a++) {
        y8[2 * a]     = yb[(8 * a + jm) * 32];
        y8[2 * a + 1] = yb[(8 * a + jm + 1) * 32];
    }

    float acc[4][4];
#pragma unroll
    for (int m = 0; m < 4; m++)
#pragma unroll
        for (int q = 0; q < 4; q++) acc[m][q] = 0.0f;

    const uint4* WH = (const uint4*)g_WfragHi;
    const uint4* WL = (const uint4*)g_WfragLo;

#pragma unroll 2
    for (int ch = 0; ch < 64; ch++) {
        // ----- build B fragment (hi + lo) in registers
        // chunk ch: k = 16*ch + kk; i = ch>>1, j = (ch&1)*16 + kk
        const float xi = xv[ch >> 1];
        const int a0i = (ch & 1) * 2;              // y8 group for k-slots 0..7
        const float p0 = xi * y8[2 * a0i];
        const float p1 = xi * y8[2 * a0i + 1];
        const float p2 = xi * y8[2 * a0i + 2];
        const float p3 = xi * y8[2 * a0i + 3];
        const uint32_t bh0 = bf16x2_of(p1, p0);
        const uint32_t bh1 = bf16x2_of(p3, p2);
        const float h0 = __uint_as_float(bh0 << 16);
        const float h1 = __uint_as_float(bh0 & 0xffff0000u);
        const float h2 = __uint_as_float(bh1 << 16);
        const float h3 = __uint_as_float(bh1 & 0xffff0000u);
        const uint32_t bl0 = bf16x2_of(p1 - h1, p0 - h0);
        const uint32_t bl1 = bf16x2_of(p3 - h3, p2 - h2);

        // ----- 4 m-tiles x 3 passes
        const int base = (ch * 4) * 32 + lane;
#pragma unroll
        for (int mt = 0; mt < 4; mt++) {
            uint4 ah = WH[base + mt * 32];
            uint4 al = WL[base + mt * 32];
            mma_bf16(acc[mt][0], acc[mt][1], acc[mt][2], acc[mt][3],
                     ah.x, ah.y, ah.z, ah.w, bh0, bh1);
            mma_bf16(acc[mt][0], acc[mt][1], acc[mt][2], acc[mt][3],
                     ah.x, ah.y, ah.z, ah.w, bl0, bl1);
            mma_bf16(acc[mt][0], acc[mt][1], acc[mt][2], acc[mt][3],
                     al.x, al.y, al.z, al.w, bh0, bh1);
        }
    }

    // ----- epilogue: out_mat + partial d-sums
    // D fragment: rows c = 16*mt + lane/4 (+8), cols d = dbase + 2*(lane%4) + {0,1}
    const int g = lane >> 2;
    const int d0 = dbase + 2 * (lane & 3);
    float* om = out_mat + (size_t)b * (NC * DD);
#pragma unroll
    for (int mt = 0; mt < 4; mt++) {
        int c0 = 16 * mt + g;
        *(float2*)&om[c0 * DD + d0] = make_float2(acc[mt][0], acc[mt][1]);
        *(float2*)&om[(c0 + 8) * DD + d0] = make_float2(acc[mt][2], acc[mt][3]);

        // sum over this warp's 8 d's: pairwise in-thread, then across quad lanes
        float s0 = acc[mt][0] + acc[mt][1];
        float s1 = acc[mt][2] + acc[mt][3];
#pragma unroll
        for (int o = 1; o <= 2; o <<= 1) {
            s0 += __shfl_xor_sync(0xffffffffu, s0, o);
            s1 += __shfl_xor_sync(0xffffffffu, s1, o);
        }
        if ((lane & 3) == 0) {
            atomicAdd(&pfin[bl][c0], s0);
            atomicAdd(&pfin[bl][c0 + 8], s1);
        }
    }
    __syncthreads();
    if (t < 2 * NC) {
        int bb = t >> 6, c = t & 63;
        out_fin[(size_t)(blockIdx.x * 2 + bb) * NC + c] = pfin[bb][c];
    }
}

extern "C" void kernel_launch(void* const* d_in, const int* in_sizes, int n_in,
                              void* d_out, int out_size) {
    const float* X = (const float*)d_in[0];
    const float* Y = (const float*)d_in[1];
    const float* K = (const float*)d_in[2];
    float* om = (float*)d_out;
    float* fin = om + (size_t)NB * NC * DD;

    wfrag_kernel<<<32, 256>>>(K);
    cin_mma_kernel<<<NB / 2, 256>>>(X, Y, om, fin);
}

// round 4
// speedup vs baseline: 4.7922x; 1.3043x over previous
#include <cuda_runtime.h>
#include <cuda_bf16.h>
#include <cstdint>

#define NB 4096
#define NC 64
#define DD 32
#define KK 1024   // H1*H2

// ---------------------------------------------------------------- W fragments
// bf16 hi/lo split, laid out per mma.sync A-fragment:
// Wfrag[chunk(64)][mtile(4)][lane(32)][reg(4)] as u32(bf16x2).
__device__ __align__(16) uint32_t g_WfragHi[64 * 4 * 32 * 4];
__device__ __align__(16) uint32_t g_WfragLo[64 * 4 * 32 * 4];

__global__ void wfrag_kernel(const float* __restrict__ K) {
    int idx = blockIdx.x * blockDim.x + threadIdx.x;  // 8192
    int lane = idx & 31;
    int mt = (idx >> 5) & 3;
    int ch = idx >> 7;
    int r0 = 16 * mt + (lane >> 2);
    int kc = 16 * ch + (lane & 3) * 2;
    uint32_t hi[4], lo[4];
#pragma unroll
    for (int q = 0; q < 4; q++) {
        int r = r0 + (q & 1) * 8;
        int c = kc + (q >> 1) * 8;
        float w0 = K[r * KK + c], w1 = K[r * KK + c + 1];
        __nv_bfloat16 h0 = __float2bfloat16_rn(w0);
        __nv_bfloat16 h1 = __float2bfloat16_rn(w1);
        __nv_bfloat16 l0 = __float2bfloat16_rn(w0 - __bfloat162float(h0));
        __nv_bfloat16 l1 = __float2bfloat16_rn(w1 - __bfloat162float(h1));
        hi[q] = (uint32_t)__bfloat16_as_ushort(h0) |
                ((uint32_t)__bfloat16_as_ushort(h1) << 16);
        lo[q] = (uint32_t)__bfloat16_as_ushort(l0) |
                ((uint32_t)__bfloat16_as_ushort(l1) << 16);
    }
    *(uint4*)&g_WfragHi[idx * 4] = make_uint4(hi[0], hi[1], hi[2], hi[3]);
    *(uint4*)&g_WfragLo[idx * 4] = make_uint4(lo[0], lo[1], lo[2], lo[3]);
}

// ---------------------------------------------------------------- helpers
__device__ __forceinline__ uint32_t bf16x2_of(float hi, float lo) {
    uint32_t r;
    asm("cvt.rn.bf16x2.f32 %0, %1, %2;" : "=r"(r) : "f"(hi), "f"(lo));
    return r;
}
__device__ __forceinline__ void mma_bf16(float& c0, float& c1, float& c2, float& c3,
                                         uint32_t a0, uint32_t a1, uint32_t a2,
                                         uint32_t a3, uint32_t b0, uint32_t b1) {
    asm volatile(
        "mma.sync.aligned.m16n8k16.row.col.f32.bf16.bf16.f32 "
        "{%0,%1,%2,%3}, {%4,%5,%6,%7}, {%8,%9}, {%0,%1,%2,%3};"
        : "+f"(c0), "+f"(c1), "+f"(c2), "+f"(c3)
        : "r"(a0), "r"(a1), "r"(a2), "r"(a3), "r"(b0), "r"(b1));
}

// Build the 4 B-fragment regs (hi pair + lo pair) for one d-column.
__device__ __forceinline__ void build_bfrag(float xi, const float* y8, int a0i,
                                            uint32_t& bh0, uint32_t& bh1,
                                            uint32_t& bl0, uint32_t& bl1) {
    float p0 = xi * y8[2 * a0i];
    float p1 = xi * y8[2 * a0i + 1];
    float p2 = xi * y8[2 * a0i + 2];
    float p3 = xi * y8[2 * a0i + 3];
    bh0 = bf16x2_of(p1, p0);
    bh1 = bf16x2_of(p3, p2);
    float h0 = __uint_as_float(bh0 << 16);
    float h1 = __uint_as_float(bh0 & 0xffff0000u);
    float h2 = __uint_as_float(bh1 << 16);
    float h3 = __uint_as_float(bh1 & 0xffff0000u);
    bl0 = bf16x2_of(p1 - h1, p0 - h0);
    bl1 = bf16x2_of(p3 - h3, p2 - h2);
}

// ---------------------------------------------------------------- main kernel
// CTA: 256 threads = 8 warps = 4 batches; 2 warps per batch, each warp
// covers 16 d-columns (2 B-fragment pairs). A-fragment loaded once per
// mtile feeds 6 MMAs (2 nfrags x 3 precision passes).
__global__ __launch_bounds__(256, 2)
void cin_mma_kernel(const float* __restrict__ X, const float* __restrict__ Y,
                    float* __restrict__ out_mat, float* __restrict__ out_fin) {
    __shared__ float x_s[4 * KK];      // x[b0..b0+3, :, :]
    __shared__ float pfin[4][NC];

    const int t = threadIdx.x;
    const int lane = t & 31;
    const int w = t >> 5;
    const int bl = w >> 1;             // local batch 0..3
    const int dbase = (w & 1) * 16;    // this warp's d range: [dbase, dbase+16)
    const int b = blockIdx.x * 4 + bl;
    const int d1 = dbase + (lane >> 2);
    const int d2 = d1 + 8;
    const int jm = (lane & 3) * 2;

    // stage x for the CTA's 4 batches (coalesced) + zero pfin
    {
        const float* xg = X + (size_t)blockIdx.x * 4 * KK;
#pragma unroll
        for (int rep = 0; rep < 16; rep++) x_s[rep * 256 + t] = xg[rep * 256 + t];
    }
    if (t < 4 * NC) ((float*)pfin)[t] = 0.0f;
    __syncthreads();

    // y values this thread's B slots need, for both d's
    const float* yb = Y + (size_t)b * KK;
    float y8a[8], y8b[8];
#pragma unroll
    for (int a = 0; a < 4; a++) {
        y8a[2 * a]     = yb[(8 * a + jm) * 32 + d1];
        y8a[2 * a + 1] = yb[(8 * a + jm + 1) * 32 + d1];
        y8b[2 * a]     = yb[(8 * a + jm) * 32 + d2];
        y8b[2 * a + 1] = yb[(8 * a + jm + 1) * 32 + d2];
    }

    float acc[4][2][4];
#pragma unroll
    for (int m = 0; m < 4; m++)
#pragma unroll
        for (int n = 0; n < 2; n++)
#pragma unroll
            for (int q = 0; q < 4; q++) acc[m][n][q] = 0.0f;

    const uint4* WH = (const uint4*)g_WfragHi;
    const uint4* WL = (const uint4*)g_WfragLo;
    const float* xrow = x_s + bl * KK;

#pragma unroll 2
    for (int ch = 0; ch < 64; ch++) {
        const int i = ch >> 1;
        const float xi1 = xrow[i * 32 + d1];
        const float xi2 = xrow[i * 32 + d2];
        const int a0i = (ch & 1) * 2;

        uint32_t bh0a, bh1a, bl0a, bl1a, bh0b, bh1b, bl0b, bl1b;
        build_bfrag(xi1, y8a, a0i, bh0a, bh1a, bl0a, bl1a);
        build_bfrag(xi2, y8b, a0i, bh0b, bh1b, bl0b, bl1b);

        const int base = ch * 128 + lane;
#pragma unroll
        for (int mt = 0; mt < 4; mt++) {
            uint4 ah = WH[base + mt * 32];
            uint4 al = WL[base + mt * 32];
            mma_bf16(acc[mt][0][0], acc[mt][0][1], acc[mt][0][2], acc[mt][0][3],
                     ah.x, ah.y, ah.z, ah.w, bh0a, bh1a);
            mma_bf16(acc[mt][0][0], acc[mt][0][1], acc[mt][0][2], acc[mt][0][3],
                     ah.x, ah.y, ah.z, ah.w, bl0a, bl1a);
            mma_bf16(acc[mt][0][0], acc[mt][0][1], acc[mt][0][2], acc[mt][0][3],
                     al.x, al.y, al.z, al.w, bh0a, bh1a);
            mma_bf16(acc[mt][1][0], acc[mt][1][1], acc[mt][1][2], acc[mt][1][3],
                     ah.x, ah.y, ah.z, ah.w, bh0b, bh1b);
            mma_bf16(acc[mt][1][0], acc[mt][1][1], acc[mt][1][2], acc[mt][1][3],
                     ah.x, ah.y, ah.z, ah.w, bl0b, bl1b);
            mma_bf16(acc[mt][1][0], acc[mt][1][1], acc[mt][1][2], acc[mt][1][3],
                     al.x, al.y, al.z, al.w, bh0b, bh1b);
        }
    }

    // ----- epilogue
    // D fragment (m16n8): rows c = 16*mt + lane/4 (+8), cols nf*8 + dbase + 2*(lane&3)+{0,1}
    const int g = lane >> 2;
    float* om = out_mat + (size_t)b * (NC * DD);
#pragma unroll
    for (int mt = 0; mt < 4; mt++) {
        int c0 = 16 * mt + g;
#pragma unroll
        for (int nf = 0; nf < 2; nf++) {
            int d0 = nf * 8 + dbase + 2 * (lane & 3);
            *(float2*)&om[c0 * DD + d0] =
                make_float2(acc[mt][nf][0], acc[mt][nf][1]);
            *(float2*)&om[(c0 + 8) * DD + d0] =
                make_float2(acc[mt][nf][2], acc[mt][nf][3]);
        }
        // d-sum over this warp's 16 columns for rows c0 and c0+8
        float s0 = acc[mt][0][0] + acc[mt][0][1] + acc[mt][1][0] + acc[mt][1][1];
        float s1 = acc[mt][0][2] + acc[mt][0][3] + acc[mt][1][2] + acc[mt][1][3];
#pragma unroll
        for (int o = 1; o <= 2; o <<= 1) {
            s0 += __shfl_xor_sync(0xffffffffu, s0, o);
            s1 += __shfl_xor_sync(0xffffffffu, s1, o);
        }
        if ((lane & 3) == 0) {
            atomicAdd(&pfin[bl][c0], s0);
            atomicAdd(&pfin[bl][c0 + 8], s1);
        }
    }
    __syncthreads();
    if (t < 4 * NC) {
        int bb = t >> 6, c = t & 63;
        out_fin[(size_t)(blockIdx.x * 4 + bb) * NC + c] = pfin[bb][c];
    }
}

extern "C" void kernel_launch(void* const* d_in, const int* in_sizes, int n_in,
                              void* d_out, int out_size) {
    const float* X = (const float*)d_in[0];
    const float* Y = (const float*)d_in[1];
    const float* K = (const float*)d_in[2];
    float* om = (float*)d_out;
    float* fin = om + (size_t)NB * NC * DD;

    wfrag_kernel<<<32, 256>>>(K);
    cin_mma_kernel<<<NB / 4, 256>>>(X, Y, om, fin);
}

// round 5
// speedup vs baseline: 5.6523x; 1.1795x over previous
#include <cuda_runtime.h>
#include <cuda_bf16.h>
#include <cstdint>

#define NB 4096
#define NC 64
#define DD 32
#define KK 1024   // H1*H2

// ---------------------------------------------------------------- W fragments
// K matrix pre-converted to tf32, laid out per mma.m16n8k8 A-fragment:
// g_Wtf[ch(64)][mt(4)][half(2)][lane(32)][q(4)]  (u32 tf32 bits) = 256 KB.
// A frag (m16k8, row): q0:(r, kk) q1:(r+8, kk) q2:(r, kk+4) q3:(r+8, kk+4),
// r = 16*mt + lane/4, kk = lane%4; global k = ch*16 + half*8 + kk.
__device__ __align__(16) uint32_t g_Wtf[64 * 4 * 2 * 32 * 4];

__global__ void wfrag_kernel(const float* __restrict__ K) {
    int idx = blockIdx.x * blockDim.x + threadIdx.x;  // 65536
    int q = idx & 3, lane = (idx >> 2) & 31;
    int half = (idx >> 7) & 1, mt = (idx >> 8) & 3, ch = idx >> 10;
    int r = 16 * mt + (q & 1) * 8 + (lane >> 2);
    int k = ch * 16 + half * 8 + (lane & 3) + (q >> 1) * 4;
    float w = K[r * KK + k];
    uint32_t v;
    asm("cvt.rna.tf32.f32 %0, %1;" : "=r"(v) : "f"(w));
    g_Wtf[idx] = v;
}

// ---------------------------------------------------------------- helpers
__device__ __forceinline__ uint32_t tf32_of(float f) {
    uint32_t r;
    asm("cvt.rna.tf32.f32 %0, %1;" : "=r"(r) : "f"(f));
    return r;
}
__device__ __forceinline__ void mma_tf32(float& c0, float& c1, float& c2, float& c3,
                                         uint32_t a0, uint32_t a1, uint32_t a2,
                                         uint32_t a3, uint32_t b0, uint32_t b1) {
    asm volatile(
        "mma.sync.aligned.m16n8k8.row.col.f32.tf32.tf32.f32 "
        "{%0,%1,%2,%3}, {%4,%5,%6,%7}, {%8,%9}, {%0,%1,%2,%3};"
        : "+f"(c0), "+f"(c1), "+f"(c2), "+f"(c3)
        : "r"(a0), "r"(a1), "r"(a2), "r"(a3), "r"(b0), "r"(b1));
}

// ---------------------------------------------------------------- main kernel
// CTA: 256 threads = 8 warps = 8 batches. One warp per batch, covering all
// 32 d-columns (4 B fragments). Each A-fragment pair (2 LDG.128) feeds 8 MMAs.
// Per-batch GEMM: OUT[c(64), d(32)] = W[c,k] * Z[k,d], K=1024, tf32 single pass.
__global__ __launch_bounds__(256, 1)
void cin_mma_kernel(const float* __restrict__ X, const float* __restrict__ Y,
                    float* __restrict__ out_mat, float* __restrict__ out_fin) {
    __shared__ float x_s[8 * KK];   // 32 KB: x for the CTA's 8 batches

    const int t = threadIdx.x;
    const int lane = t & 31;
    const int w = t >> 5;
    const int b = blockIdx.x * 8 + w;
    const int g = lane >> 2;        // row group / d offset
    const int jm = lane & 3;

    // stage x (coalesced float4)
    {
        const float4* xg = (const float4*)(X + (size_t)blockIdx.x * 8 * KK);
        float4* xs4 = (float4*)x_s;
#pragma unroll
        for (int rep = 0; rep < 8; rep++) xs4[rep * 256 + t] = xg[rep * 256 + t];
    }
    __syncthreads();

    // y values this thread's B-fragment slots need: j = jm + 4s, s = 0..7,
    // for each of the 4 d-columns d = g + 8*nf.
    const float* yb = Y + (size_t)b * KK;
    float y8[4][8];
#pragma unroll
    for (int nf = 0; nf < 4; nf++) {
        int d = g + 8 * nf;
#pragma unroll
        for (int s = 0; s < 8; s++) y8[nf][s] = yb[(4 * s + jm) * 32 + d];
    }

    float acc[4][4][4];
#pragma unroll
    for (int m = 0; m < 4; m++)
#pragma unroll
        for (int n = 0; n < 4; n++)
#pragma unroll
            for (int q = 0; q < 4; q++) acc[m][n][q] = 0.0f;

    const uint4* W4 = (const uint4*)g_Wtf;  // [ch*256 + mt*64 + half*32 + lane]
    const float* xrow = x_s + w * KK;

#pragma unroll 2
    for (int ch = 0; ch < 64; ch++) {
        const int i = ch >> 1;
        const int p = ch & 1;

        // B fragments: bf[nf][2*half+u] = tf32( x[b,i,d] * y[b, j, d] ),
        // j = p*16 + half*8 + jm + 4*u, d = g + 8*nf.
        uint32_t bf[4][4];
#pragma unroll
        for (int nf = 0; nf < 4; nf++) {
            const float xi = xrow[i * 32 + g + 8 * nf];
            bf[nf][0] = tf32_of(xi * y8[nf][4 * p + 0]);
            bf[nf][1] = tf32_of(xi * y8[nf][4 * p + 1]);
            bf[nf][2] = tf32_of(xi * y8[nf][4 * p + 2]);
            bf[nf][3] = tf32_of(xi * y8[nf][4 * p + 3]);
        }

        const int base = ch * 256 + lane;
#pragma unroll
        for (int mt = 0; mt < 4; mt++) {
            uint4 a0 = W4[base + mt * 64];        // k-half 0
            uint4 a1 = W4[base + mt * 64 + 32];   // k-half 1
#pragma unroll
            for (int nf = 0; nf < 4; nf++) {
                mma_tf32(acc[mt][nf][0], acc[mt][nf][1], acc[mt][nf][2],
                         acc[mt][nf][3], a0.x, a0.y, a0.z, a0.w,
                         bf[nf][0], bf[nf][1]);
                mma_tf32(acc[mt][nf][0], acc[mt][nf][1], acc[mt][nf][2],
                         acc[mt][nf][3], a1.x, a1.y, a1.z, a1.w,
                         bf[nf][2], bf[nf][3]);
            }
        }
    }

    // ----- epilogue: D frag rows c = 16*mt + g (+8), cols d = 8*nf + 2*jm + {0,1}
    float* om = out_mat + (size_t)b * (NC * DD);
    float* fb = out_fin + (size_t)b * NC;
#pragma unroll
    for (int mt = 0; mt < 4; mt++) {
        const int c0 = 16 * mt + g;
        float s0 = 0.0f, s1 = 0.0f;
#pragma unroll
        for (int nf = 0; nf < 4; nf++) {
            int d0 = 8 * nf + 2 * jm;
            *(float2*)&om[c0 * DD + d0] =
                make_float2(acc[mt][nf][0], acc[mt][nf][1]);
            *(float2*)&om[(c0 + 8) * DD + d0] =
                make_float2(acc[mt][nf][2], acc[mt][nf][3]);
            s0 += acc[mt][nf][0] + acc[mt][nf][1];
            s1 += acc[mt][nf][2] + acc[mt][nf][3];
        }
        // sum across the quad (lanes sharing g): covers all 32 d
#pragma unroll
        for (int o = 1; o <= 2; o <<= 1) {
            s0 += __shfl_xor_sync(0xffffffffu, s0, o);
            s1 += __shfl_xor_sync(0xffffffffu, s1, o);
        }
        if (jm == 0) { fb[c0] = s0; fb[c0 + 8] = s1; }
    }
}

extern "C" void kernel_launch(void* const* d_in, const int* in_sizes, int n_in,
                              void* d_out, int out_size) {
    const float* X = (const float*)d_in[0];
    const float* Y = (const float*)d_in[1];
    const float* K = (const float*)d_in[2];
    float* om = (float*)d_out;
    float* fin = om + (size_t)NB * NC * DD;

    wfrag_kernel<<<256, 256>>>(K);
    cin_mma_kernel<<<NB / 8, 256>>>(X, Y, om, fin);
}

// round 6
// speedup vs baseline: 5.8714x; 1.0388x over previous
#include <cuda_runtime.h>
#include <cuda_bf16.h>
#include <cstdint>

#define NB 4096
#define NC 64
#define DD 32
#define KK 1024   // H1*H2

// ---------------------------------------------------------------- W fragments
// K matrix pre-converted to tf32, laid out per mma.m16n8k8 A-fragment:
// g_Wtf[ch(64)][mt(4)][half(2)][lane(32)][q(4)]  (u32 tf32 bits) = 256 KB.
// A frag (m16k8, row): q0:(r, kk) q1:(r+8, kk) q2:(r, kk+4) q3:(r+8, kk+4),
// r = 16*mt + lane/4, kk = lane%4; global k = ch*16 + half*8 + kk.
__device__ __align__(16) uint32_t g_Wtf[64 * 4 * 2 * 32 * 4];

__global__ void wfrag_kernel(const float* __restrict__ K) {
    int idx = blockIdx.x * blockDim.x + threadIdx.x;  // 65536
    int q = idx & 3, lane = (idx >> 2) & 31;
    int half = (idx >> 7) & 1, mt = (idx >> 8) & 3, ch = idx >> 10;
    int r = 16 * mt + (q & 1) * 8 + (lane >> 2);
    int k = ch * 16 + half * 8 + (lane & 3) + (q >> 1) * 4;
    float w = K[r * KK + k];
    uint32_t v;
    asm("cvt.rna.tf32.f32 %0, %1;" : "=r"(v) : "f"(w));
    g_Wtf[idx] = v;
}

// ---------------------------------------------------------------- helpers
__device__ __forceinline__ uint32_t tf32_of(float f) {
    uint32_t r;
    asm("cvt.rna.tf32.f32 %0, %1;" : "=r"(r) : "f"(f));
    return r;
}
__device__ __forceinline__ void mma_tf32(float& c0, float& c1, float& c2, float& c3,
                                         uint32_t a0, uint32_t a1, uint32_t a2,
                                         uint32_t a3, uint32_t b0, uint32_t b1) {
    asm volatile(
        "mma.sync.aligned.m16n8k8.row.col.f32.tf32.tf32.f32 "
        "{%0,%1,%2,%3}, {%4,%5,%6,%7}, {%8,%9}, {%0,%1,%2,%3};"
        : "+f"(c0), "+f"(c1), "+f"(c2), "+f"(c3)
        : "r"(a0), "r"(a1), "r"(a2), "r"(a3), "r"(b0), "r"(b1));
}

// ---------------------------------------------------------------- main kernel
// CTA: 256 threads = 8 warps = 4 batches; 2 warps per batch, m-split:
// warp (w&1) covers m-tiles {2*(w&1), 2*(w&1)+1} for all 32 d-columns.
// B fragments built per warp (duplicated across the batch's 2 warps).
// Per-batch GEMM: OUT[c(64), d(32)] = W[c,k] * Z[k,d], K=1024, tf32 1-pass.
__global__ __launch_bounds__(256, 2)
void cin_mma_kernel(const float* __restrict__ X, const float* __restrict__ Y,
                    float* __restrict__ out_mat, float* __restrict__ out_fin) {
    __shared__ float x_s[4 * KK];   // 16 KB: x for the CTA's 4 batches

    const int t = threadIdx.x;
    const int lane = t & 31;
    const int w = t >> 5;
    const int bl = w >> 1;            // local batch 0..3
    const int mh = w & 1;             // m-half: m-tiles {2*mh, 2*mh+1}
    const int b = blockIdx.x * 4 + bl;
    const int g = lane >> 2;          // row group / d offset
    const int jm = lane & 3;

    // stage x (coalesced float4)
    {
        const float4* xg = (const float4*)(X + (size_t)blockIdx.x * 4 * KK);
        float4* xs4 = (float4*)x_s;
#pragma unroll
        for (int rep = 0; rep < 4; rep++) xs4[rep * 256 + t] = xg[rep * 256 + t];
    }
    __syncthreads();

    // y values this thread's B-fragment slots need: j = jm + 4s, s = 0..7,
    // for each of the 4 d-columns d = g + 8*nf.
    const float* yb = Y + (size_t)b * KK;
    float y8[4][8];
#pragma unroll
    for (int nf = 0; nf < 4; nf++) {
        int d = g + 8 * nf;
#pragma unroll
        for (int s = 0; s < 8; s++) y8[nf][s] = yb[(4 * s + jm) * 32 + d];
    }

    float acc[2][4][4];
#pragma unroll
    for (int m = 0; m < 2; m++)
#pragma unroll
        for (int n = 0; n < 4; n++)
#pragma unroll
            for (int q = 0; q < 4; q++) acc[m][n][q] = 0.0f;

    const uint4* W4 = (const uint4*)g_Wtf;  // [ch*256 + mt*64 + half*32 + lane]
    const float* xrow = x_s + bl * KK;

#pragma unroll 2
    for (int ch = 0; ch < 64; ch++) {
        const int i = ch >> 1;
        const int p = ch & 1;

        // B fragments: bf[nf][2*half+u] = tf32( x[b,i,d] * y[b,j,d] ),
        // j = p*16 + half*8 + jm + 4*u, d = g + 8*nf.
        uint32_t bf[4][4];
#pragma unroll
        for (int nf = 0; nf < 4; nf++) {
            const float xi = xrow[i * 32 + g + 8 * nf];
            bf[nf][0] = tf32_of(xi * y8[nf][4 * p + 0]);
            bf[nf][1] = tf32_of(xi * y8[nf][4 * p + 1]);
            bf[nf][2] = tf32_of(xi * y8[nf][4 * p + 2]);
            bf[nf][3] = tf32_of(xi * y8[nf][4 * p + 3]);
        }

        const int base = ch * 256 + lane;
#pragma unroll
        for (int m = 0; m < 2; m++) {
            const int mt = 2 * mh + m;
            uint4 a0 = W4[base + mt * 64];        // k-half 0
            uint4 a1 = W4[base + mt * 64 + 32];   // k-half 1
#pragma unroll
            for (int nf = 0; nf < 4; nf++) {
                mma_tf32(acc[m][nf][0], acc[m][nf][1], acc[m][nf][2],
                         acc[m][nf][3], a0.x, a0.y, a0.z, a0.w,
                         bf[nf][0], bf[nf][1]);
                mma_tf32(acc[m][nf][0], acc[m][nf][1], acc[m][nf][2],
                         acc[m][nf][3], a1.x, a1.y, a1.z, a1.w,
                         bf[nf][2], bf[nf][3]);
            }
        }
    }

    // ----- epilogue: D frag rows c = 16*(2*mh+m) + g (+8),
    // cols d = 8*nf + 2*jm + {0,1}. Each warp owns distinct c rows.
    float* om = out_mat + (size_t)b * (NC * DD);
    float* fb = out_fin + (size_t)b * NC;
#pragma unroll
    for (int m = 0; m < 2; m++) {
        const int c0 = 16 * (2 * mh + m) + g;
        float s0 = 0.0f, s1 = 0.0f;
#pragma unroll
        for (int nf = 0; nf < 4; nf++) {
            int d0 = 8 * nf + 2 * jm;
            *(float2*)&om[c0 * DD + d0] =
                make_float2(acc[m][nf][0], acc[m][nf][1]);
            *(float2*)&om[(c0 + 8) * DD + d0] =
                make_float2(acc[m][nf][2], acc[m][nf][3]);
            s0 += acc[m][nf][0] + acc[m][nf][1];
            s1 += acc[m][nf][2] + acc[m][nf][3];
        }
        // sum across the quad (lanes sharing g): covers all 32 d
#pragma unroll
        for (int o = 1; o <= 2; o <<= 1) {
            s0 += __shfl_xor_sync(0xffffffffu, s0, o);
            s1 += __shfl_xor_sync(0xffffffffu, s1, o);
        }
        if (jm == 0) { fb[c0] = s0; fb[c0 + 8] = s1; }
    }
}

extern "C" void kernel_launch(void* const* d_in, const int* in_sizes, int n_in,
                              void* d_out, int out_size) {
    const float* X = (const float*)d_in[0];
    const float* Y = (const float*)d_in[1];
    const float* K = (const float*)d_in[2];
    float* om = (float*)d_out;
    float* fin = om + (size_t)NB * NC * DD;

    wfrag_kernel<<<256, 256>>>(K);
    cin_mma_kernel<<<NB / 4, 256>>>(X, Y, om, fin);
}

// round 7
// speedup vs baseline: 9.7125x; 1.6542x over previous
#include <cuda_runtime.h>
#include <cuda_fp16.h>
#include <cstdint>

#define NB 4096
#define NC 64
#define DD 32
#define KK 1024   // H1*H2

// ---------------------------------------------------------------- W fragments
// K matrix pre-converted to fp16, laid out per mma.m16n8k16 A-fragment:
// g_Wf16[ch(64)][mt(4)][lane(32)] = uint4 {a0,a1,a2,a3} (each fp16x2) = 128 KB.
// a0=(r, k0|k0+1) a1=(r+8, k0|k0+1) a2=(r, k0+8|k0+9) a3=(r+8, k0+8|k0+9),
// r = 16*mt + lane/4, k0 = 2*(lane%4); global k = 16*ch + klocal.
__device__ __align__(16) uint4 g_Wf16[64 * 4 * 32];

__global__ void wfrag_kernel(const float* __restrict__ K) {
    int idx = blockIdx.x * blockDim.x + threadIdx.x;  // 8192
    int lane = idx & 31, mt = (idx >> 5) & 3, ch = idx >> 7;
    int r0 = 16 * mt + (lane >> 2);
    int k0 = 16 * ch + 2 * (lane & 3);
    uint32_t q[4];
#pragma unroll
    for (int u = 0; u < 4; u++) {
        int r = r0 + (u & 1) * 8;
        int k = k0 + (u >> 1) * 8;
        __half2 h = __floats2half2_rn(K[r * KK + k], K[r * KK + k + 1]);
        q[u] = *(uint32_t*)&h;
    }
    g_Wf16[idx] = make_uint4(q[0], q[1], q[2], q[3]);
}

// ---------------------------------------------------------------- helpers
__device__ __forceinline__ uint32_t f16x2_of(float hi, float lo) {
    uint32_t r;
    asm("cvt.rn.f16x2.f32 %0, %1, %2;" : "=r"(r) : "f"(hi), "f"(lo));
    return r;
}
__device__ __forceinline__ void mma_f16(float& c0, float& c1, float& c2, float& c3,
                                        uint32_t a0, uint32_t a1, uint32_t a2,
                                        uint32_t a3, uint32_t b0, uint32_t b1) {
    asm volatile(
        "mma.sync.aligned.m16n8k16.row.col.f32.f16.f16.f32 "
        "{%0,%1,%2,%3}, {%4,%5,%6,%7}, {%8,%9}, {%0,%1,%2,%3};"
        : "+f"(c0), "+f"(c1), "+f"(c2), "+f"(c3)
        : "r"(a0), "r"(a1), "r"(a2), "r"(a3), "r"(b0), "r"(b1));
}

// ---------------------------------------------------------------- main kernel
// CTA: 256 threads = 8 warps = 4 batches; 2 warps per batch (m-split):
// warp (w&1) covers m-tiles {2*(w&1), 2*(w&1)+1} for all 32 d-columns.
// Per-batch GEMM: OUT[c(64), d(32)] = W[c,k] * Z[k,d], K=1024,
// fp16 single pass (fp16 mantissa == tf32 mantissa; f32 accumulate).
// k16 chunk ch: i = ch>>1, j = (ch&1)*16 + klocal.
__global__ __launch_bounds__(256, 2)
void cin_mma_kernel(const float* __restrict__ X, const float* __restrict__ Y,
                    float* __restrict__ out_mat, float* __restrict__ out_fin) {
    __shared__ float x_s[4 * KK];   // 16 KB: x for the CTA's 4 batches

    const int t = threadIdx.x;
    const int lane = t & 31;
    const int w = t >> 5;
    const int bl = w >> 1;            // local batch 0..3
    const int mh = w & 1;             // m-half: m-tiles {2*mh, 2*mh+1}
    const int b = blockIdx.x * 4 + bl;
    const int g = lane >> 2;          // row group / d offset
    const int jm = lane & 3;

    // stage x (coalesced float4)
    {
        const float4* xg = (const float4*)(X + (size_t)blockIdx.x * 4 * KK);
        float4* xs4 = (float4*)x_s;
#pragma unroll
        for (int rep = 0; rep < 4; rep++) xs4[rep * 256 + t] = xg[rep * 256 + t];
    }
    __syncthreads();

    // y values this thread's B-fragment slots need.
    // B frag (n8k16 col): b0 <- klocal {2jm, 2jm+1}, b1 <- {2jm+8, 2jm+9};
    // j = p*16 + klocal. Store y8[nf][4p+u]: u=0,1 -> j=16p+2jm+u;
    // u=2,3 -> j=16p+8+2jm+(u-2). d = g + 8*nf.
    const float* yb = Y + (size_t)b * KK;
    float y8[4][8];
#pragma unroll
    for (int nf = 0; nf < 4; nf++) {
        int d = g + 8 * nf;
#pragma unroll
        for (int p = 0; p < 2; p++) {
            y8[nf][4 * p + 0] = yb[(16 * p + 2 * jm) * 32 + d];
            y8[nf][4 * p + 1] = yb[(16 * p + 2 * jm + 1) * 32 + d];
            y8[nf][4 * p + 2] = yb[(16 * p + 8 + 2 * jm) * 32 + d];
            y8[nf][4 * p + 3] = yb[(16 * p + 8 + 2 * jm + 1) * 32 + d];
        }
    }

    float acc[2][4][4];
#pragma unroll
    for (int m = 0; m < 2; m++)
#pragma unroll
        for (int n = 0; n < 4; n++)
#pragma unroll
            for (int q = 0; q < 4; q++) acc[m][n][q] = 0.0f;

    const uint4* W4 = g_Wf16;          // [ch*128 + mt*32 + lane]
    const float* xrow = x_s + bl * KK;

#pragma unroll 2
    for (int ch = 0; ch < 64; ch++) {
        const int i = ch >> 1;
        const int p = ch & 1;

        // B fragments (fp16x2): bf[nf][0] = {Z(k0),Z(k0+1)}, bf[nf][1] = {+8}
        uint32_t bf[4][2];
#pragma unroll
        for (int nf = 0; nf < 4; nf++) {
            const float xi = xrow[i * 32 + g + 8 * nf];
            bf[nf][0] = f16x2_of(xi * y8[nf][4 * p + 1], xi * y8[nf][4 * p + 0]);
            bf[nf][1] = f16x2_of(xi * y8[nf][4 * p + 3], xi * y8[nf][4 * p + 2]);
        }

        const int base = ch * 128 + lane;
#pragma unroll
        for (int m = 0; m < 2; m++) {
            const int mt = 2 * mh + m;
            uint4 a = W4[base + mt * 32];
#pragma unroll
            for (int nf = 0; nf < 4; nf++)
                mma_f16(acc[m][nf][0], acc[m][nf][1], acc[m][nf][2],
                        acc[m][nf][3], a.x, a.y, a.z, a.w,
                        bf[nf][0], bf[nf][1]);
        }
    }

    // ----- epilogue: D frag rows c = 16*(2*mh+m) + g (+8),
    // cols d = 8*nf + 2*jm + {0,1}. Each warp owns distinct c rows.
    float* om = out_mat + (size_t)b * (NC * DD);
    float* fb = out_fin + (size_t)b * NC;
#pragma unroll
    for (int m = 0; m < 2; m++) {
        const int c0 = 16 * (2 * mh + m) + g;
        float s0 = 0.0f, s1 = 0.0f;
#pragma unroll
        for (int nf = 0; nf < 4; nf++) {
            int d0 = 8 * nf + 2 * jm;
            *(float2*)&om[c0 * DD + d0] =
                make_float2(acc[m][nf][0], acc[m][nf][1]);
            *(float2*)&om[(c0 + 8) * DD + d0] =
                make_float2(acc[m][nf][2], acc[m][nf][3]);
            s0 += acc[m][nf][0] + acc[m][nf][1];
            s1 += acc[m][nf][2] + acc[m][nf][3];
        }
        // sum across the quad (lanes sharing g): covers all 32 d
#pragma unroll
        for (int o = 1; o <= 2; o <<= 1) {
            s0 += __shfl_xor_sync(0xffffffffu, s0, o);
            s1 += __shfl_xor_sync(0xffffffffu, s1, o);
        }
        if (jm == 0) { fb[c0] = s0; fb[c0 + 8] = s1; }
    }
}

extern "C" void kernel_launch(void* const* d_in, const int* in_sizes, int n_in,
                              void* d_out, int out_size) {
    const float* X = (const float*)d_in[0];
    const float* Y = (const float*)d_in[1];
    const float* K = (const float*)d_in[2];
    float* om = (float*)d_out;
    float* fin = om + (size_t)NB * NC * DD;

    wfrag_kernel<<<32, 256>>>(K);
    cin_mma_kernel<<<NB / 4, 256>>>(X, Y, om, fin);
}